// round 1
// baseline (speedup 1.0000x reference)
#include <cuda_runtime.h>
#include <cstdint>
#include <math.h>

#define T_TOKENS 4096
#define DMODEL   1024
#define DFF      2048
#define NEXP     8

// ---------------- scratch (device globals; no runtime alloc) ----------------
__device__ int   g_counts[NEXP];
__device__ int   g_elist[NEXP][T_TOKENS];
__device__ float g_egate[NEXP][T_TOKENS];
// act scratch: [E][T][DFF] fp32. Rows >= count[e] are never written (stay 0).
__device__ float g_act[(size_t)NEXP * T_TOKENS * DFF];

// ---------------- helpers ----------------
__device__ __forceinline__ uint32_t f2tf(float x) {
    uint32_t r;
    asm("cvt.rna.tf32.f32 %0, %1;" : "=r"(r) : "f"(x));
    return r;
}

__device__ __forceinline__ void mma8(float* d, const uint32_t* a, const uint32_t* b) {
    asm volatile(
        "mma.sync.aligned.m16n8k8.row.col.f32.tf32.tf32.f32 "
        "{%0,%1,%2,%3}, {%4,%5,%6,%7}, {%8,%9}, {%0,%1,%2,%3};\n"
        : "+f"(d[0]), "+f"(d[1]), "+f"(d[2]), "+f"(d[3])
        : "r"(a[0]), "r"(a[1]), "r"(a[2]), "r"(a[3]), "r"(b[0]), "r"(b[1]));
}

// ---------------- kernel 0: zero output + counters ----------------
__global__ void k_zero(float* __restrict__ out) {
    int i = blockIdx.x * blockDim.x + threadIdx.x;
    ((float4*)out)[i] = make_float4(0.f, 0.f, 0.f, 0.f);
    if (i < NEXP) g_counts[i] = 0;
}

// ---------------- kernel 1: router (fp32 exact) ----------------
__global__ __launch_bounds__(256) void k_router(const float* __restrict__ x,
                                                const float* __restrict__ rw,
                                                float* __restrict__ logits) {
    __shared__ float4 sx4[256];
    __shared__ float  slog[NEXP];
    const int t = blockIdx.x, tid = threadIdx.x;
    sx4[tid] = ((const float4*)(x + (size_t)t * DMODEL))[tid];
    __syncthreads();
    const int w = tid >> 5, lane = tid & 31;
    const float4* r4 = (const float4*)(rw + (size_t)w * DMODEL);
    float s = 0.f;
#pragma unroll
    for (int j = 0; j < 8; j++) {
        float4 a = sx4[lane + j * 32];
        float4 b = r4[lane + j * 32];
        s += a.x * b.x + a.y * b.y + a.z * b.z + a.w * b.w;
    }
#pragma unroll
    for (int o = 16; o; o >>= 1) s += __shfl_xor_sync(0xffffffffu, s, o);
    if (lane == 0) { slog[w] = s; logits[t * NEXP + w] = s; }
    __syncthreads();
    if (tid == 0) {
        float v0 = -INFINITY, v1 = -INFINITY; int i0 = 0, i1 = 0;
#pragma unroll
        for (int e = 0; e < NEXP; e++) { float v = slog[e]; if (v > v0) { v0 = v; i0 = e; } }
#pragma unroll
        for (int e = 0; e < NEXP; e++) { if (e == i0) continue; float v = slog[e]; if (v > v1) { v1 = v; i1 = e; } }
        float ex = expf(v1 - v0);
        float inv = 1.f / (1.f + ex);
        float g0 = inv, g1 = ex * inv;
        int p0 = atomicAdd(&g_counts[i0], 1);
        g_elist[i0][p0] = t; g_egate[i0][p0] = g0;
        int p1 = atomicAdd(&g_counts[i1], 1);
        g_elist[i1][p1] = t; g_egate[i1][p1] = g1;
    }
}

// ---------------- kernel 2: grouped GEMM1 + SwiGLU ----------------
// Block tile: M=128 (gathered tokens), 128 interleaved cols = 64 (h1,h2) pairs.
// B row mapping: tile col n -> w_in row (n even: f0+n/2, n odd: DFF+f0+n/2) so
// SwiGLU pairs land in the same thread's (c0,c1)/(c2,c3) accumulator regs.
__global__ __launch_bounds__(256) void k_gemm1(const float* __restrict__ x,
                                               const float* __restrict__ w_in) {
    const int e   = blockIdx.z;
    const int cnt = g_counts[e];
    const int m0  = blockIdx.y * 128;
    if (m0 >= cnt) return;
    const int valid = min(128, cnt - m0);
    const int f0 = blockIdx.x * 64;

    __shared__ uint32_t sA[128][36];
    __shared__ uint32_t sB[128][36];
    __shared__ int sTok[128];

    const int tid = threadIdx.x;
    if (tid < 128) sTok[tid] = g_elist[e][m0 + min(tid, valid - 1)];
    __syncthreads();

    const int mbase = tid >> 3;   // 0..31
    const int kq    = tid & 7;    // float4 column
    const float* wbase = w_in + (size_t)e * (2 * DFF) * DMODEL;

    int tokv[4], wrv[4];
#pragma unroll
    for (int v = 0; v < 4; v++) {
        int m = mbase + 32 * v;
        tokv[v] = sTok[m];
        wrv[v]  = (m & 1) ? (DFF + f0 + (m >> 1)) : (f0 + (m >> 1));
    }

    float4 rA[4], rB[4];
#pragma unroll
    for (int v = 0; v < 4; v++) {
        rA[v] = *(const float4*)(x + (size_t)tokv[v] * DMODEL + kq * 4);
        rB[v] = *(const float4*)(wbase + (size_t)wrv[v] * DMODEL + kq * 4);
    }

    const int warp = tid >> 5, lane = tid & 31;
    const int wm = warp >> 2, wn = warp & 3;      // 2 x 4 warp grid
    const int g = lane >> 2, c = lane & 3;

    float acc[4][4][4];
#pragma unroll
    for (int a = 0; a < 4; a++)
#pragma unroll
        for (int b = 0; b < 4; b++)
#pragma unroll
            for (int q = 0; q < 4; q++) acc[a][b][q] = 0.f;

    const int KT = DMODEL / 32;
    for (int kt = 0; kt < KT; ++kt) {
        __syncthreads();
#pragma unroll
        for (int v = 0; v < 4; v++) {
            int m = mbase + 32 * v;
            *(uint4*)&sA[m][kq * 4] =
                make_uint4(f2tf(rA[v].x), f2tf(rA[v].y), f2tf(rA[v].z), f2tf(rA[v].w));
            *(uint4*)&sB[m][kq * 4] =
                make_uint4(f2tf(rB[v].x), f2tf(rB[v].y), f2tf(rB[v].z), f2tf(rB[v].w));
        }
        __syncthreads();
        if (kt + 1 < KT) {
            int k0 = (kt + 1) * 32;
#pragma unroll
            for (int v = 0; v < 4; v++) {
                rA[v] = *(const float4*)(x + (size_t)tokv[v] * DMODEL + k0 + kq * 4);
                rB[v] = *(const float4*)(wbase + (size_t)wrv[v] * DMODEL + k0 + kq * 4);
            }
        }
#pragma unroll
        for (int ks = 0; ks < 4; ks++) {
            const int kc = ks * 8;
            uint32_t af[4][4], bf[4][2];
#pragma unroll
            for (int mt = 0; mt < 4; mt++) {
                int r = wm * 64 + mt * 16 + g;
                af[mt][0] = sA[r][kc + c];     af[mt][1] = sA[r + 8][kc + c];
                af[mt][2] = sA[r][kc + c + 4]; af[mt][3] = sA[r + 8][kc + c + 4];
            }
#pragma unroll
            for (int nt = 0; nt < 4; nt++) {
                int n = wn * 32 + nt * 8 + g;
                bf[nt][0] = sB[n][kc + c]; bf[nt][1] = sB[n][kc + c + 4];
            }
#pragma unroll
            for (int mt = 0; mt < 4; mt++)
#pragma unroll
                for (int nt = 0; nt < 4; nt++) mma8(acc[mt][nt], af[mt], bf[nt]);
        }
    }

    // SwiGLU epilogue: pairs (c0,c1) / (c2,c3) = (h1, h2)
    float* abase = g_act + (size_t)e * T_TOKENS * DFF;
#pragma unroll
    for (int mt = 0; mt < 4; mt++) {
        int r0 = wm * 64 + mt * 16 + g;
#pragma unroll
        for (int nt = 0; nt < 4; nt++) {
            int fl = f0 + wn * 16 + nt * 4 + c;
            if (r0 < valid) {
                float a = acc[mt][nt][0], b = acc[mt][nt][1];
                abase[(size_t)(m0 + r0) * DFF + fl] = (a / (1.f + expf(-a))) * b;
            }
            if (r0 + 8 < valid) {
                float a = acc[mt][nt][2], b = acc[mt][nt][3];
                abase[(size_t)(m0 + r0 + 8) * DFF + fl] = (a / (1.f + expf(-a))) * b;
            }
        }
    }
}

// ---------------- kernel 3: grouped GEMM2 + gated scatter-add ----------------
__global__ __launch_bounds__(256) void k_gemm2(const float* __restrict__ w_out,
                                               float* __restrict__ out) {
    const int e   = blockIdx.z;
    const int cnt = g_counts[e];
    const int m0  = blockIdx.y * 128;
    if (m0 >= cnt) return;
    const int valid = min(128, cnt - m0);
    const int n0 = blockIdx.x * 128;

    __shared__ uint32_t sA[128][36];
    __shared__ uint32_t sB[128][36];
    __shared__ int   sTok[128];
    __shared__ float sGate[128];

    const int tid = threadIdx.x;
    if (tid < 128) {
        int i = m0 + min(tid, valid - 1);
        sTok[tid]  = g_elist[e][i];
        sGate[tid] = g_egate[e][i];
    }
    __syncthreads();

    const int mbase = tid >> 3;
    const int kq    = tid & 7;
    const float* abase = g_act + (size_t)e * T_TOKENS * DFF + (size_t)m0 * DFF;
    const float* bbase = w_out + (size_t)e * DMODEL * DFF + (size_t)n0 * DFF;

    float4 rA[4], rB[4];
#pragma unroll
    for (int v = 0; v < 4; v++) {
        rA[v] = *(const float4*)(abase + (size_t)(mbase + 32 * v) * DFF + kq * 4);
        rB[v] = *(const float4*)(bbase + (size_t)(mbase + 32 * v) * DFF + kq * 4);
    }

    const int warp = tid >> 5, lane = tid & 31;
    const int wm = warp >> 2, wn = warp & 3;
    const int g = lane >> 2, c = lane & 3;

    float acc[4][4][4];
#pragma unroll
    for (int a = 0; a < 4; a++)
#pragma unroll
        for (int b = 0; b < 4; b++)
#pragma unroll
            for (int q = 0; q < 4; q++) acc[a][b][q] = 0.f;

    const int KT = DFF / 32;
    for (int kt = 0; kt < KT; ++kt) {
        __syncthreads();
#pragma unroll
        for (int v = 0; v < 4; v++) {
            int m = mbase + 32 * v;
            *(uint4*)&sA[m][kq * 4] =
                make_uint4(f2tf(rA[v].x), f2tf(rA[v].y), f2tf(rA[v].z), f2tf(rA[v].w));
            *(uint4*)&sB[m][kq * 4] =
                make_uint4(f2tf(rB[v].x), f2tf(rB[v].y), f2tf(rB[v].z), f2tf(rB[v].w));
        }
        __syncthreads();
        if (kt + 1 < KT) {
            int k0 = (kt + 1) * 32;
#pragma unroll
            for (int v = 0; v < 4; v++) {
                rA[v] = *(const float4*)(abase + (size_t)(mbase + 32 * v) * DFF + k0 + kq * 4);
                rB[v] = *(const float4*)(bbase + (size_t)(mbase + 32 * v) * DFF + k0 + kq * 4);
            }
        }
#pragma unroll
        for (int ks = 0; ks < 4; ks++) {
            const int kc = ks * 8;
            uint32_t af[4][4], bf[4][2];
#pragma unroll
            for (int mt = 0; mt < 4; mt++) {
                int r = wm * 64 + mt * 16 + g;
                af[mt][0] = sA[r][kc + c];     af[mt][1] = sA[r + 8][kc + c];
                af[mt][2] = sA[r][kc + c + 4]; af[mt][3] = sA[r + 8][kc + c + 4];
            }
#pragma unroll
            for (int nt = 0; nt < 4; nt++) {
                int n = wn * 32 + nt * 8 + g;
                bf[nt][0] = sB[n][kc + c]; bf[nt][1] = sB[n][kc + c + 4];
            }
#pragma unroll
            for (int mt = 0; mt < 4; mt++)
#pragma unroll
                for (int nt = 0; nt < 4; nt++) mma8(acc[mt][nt], af[mt], bf[nt]);
        }
    }

    // gated scatter-add: each token gets exactly 2 contributions (commutative => deterministic)
#pragma unroll
    for (int mt = 0; mt < 4; mt++) {
        int r0 = wm * 64 + mt * 16 + g;
        int tok0 = sTok[r0];        float gt0 = sGate[r0];
        int tok1 = sTok[r0 + 8];    float gt1 = sGate[r0 + 8];
#pragma unroll
        for (int nt = 0; nt < 4; nt++) {
            int col = n0 + wn * 32 + nt * 8 + 2 * c;
            if (r0 < valid) {
                atomicAdd(&out[(size_t)tok0 * DMODEL + col],     gt0 * acc[mt][nt][0]);
                atomicAdd(&out[(size_t)tok0 * DMODEL + col + 1], gt0 * acc[mt][nt][1]);
            }
            if (r0 + 8 < valid) {
                atomicAdd(&out[(size_t)tok1 * DMODEL + col],     gt1 * acc[mt][nt][2]);
                atomicAdd(&out[(size_t)tok1 * DMODEL + col + 1], gt1 * acc[mt][nt][3]);
            }
        }
    }
}

// ---------------- launch ----------------
extern "C" void kernel_launch(void* const* d_in, const int* in_sizes, int n_in,
                              void* d_out, int out_size) {
    const float* x     = (const float*)d_in[0];
    const float* rw    = (const float*)d_in[1];
    const float* w_in  = (const float*)d_in[2];
    const float* w_out = (const float*)d_in[3];
    float* out    = (float*)d_out;
    float* logits = out + (size_t)T_TOKENS * DMODEL;

    k_zero<<<(T_TOKENS * DMODEL / 4) / 256, 256>>>(out);
    k_router<<<T_TOKENS, 256>>>(x, rw, logits);
    k_gemm1<<<dim3(DFF / 64, T_TOKENS / 128, NEXP), 256>>>(x, w_in);
    k_gemm2<<<dim3(DMODEL / 128, T_TOKENS / 128, NEXP), 256>>>(w_out, out);
}